// round 12
// baseline (speedup 1.0000x reference)
#include <cuda_runtime.h>
#include <math.h>

#define BB 4
#define NN 2048
#define CC 81
#define ROWS (BB * NN)          // 8192
#define IMG_W 1024.0f
#define IMG_H 800.0f
#define SCORE_THRESH 0.05f
#define NMS_THRESH 0.5f
#define DETS_PER_IMG 100
#define BBOX_CLIP 4.135166556742356f
#define P_  256                 // NMS mask prefix length
#define WP  (P_ / 64)           // 4 words per prefix row
#define SSEL 512                // selection capacity
#define TSEL 320                // selection target (>= P_ + margin)
#define NBLK 128
#define NTHR 1024
#define NWARPS (NBLK * NTHR / 32)   // 4096
#define RPW (ROWS / NWARPS)         // 2 rows per warp

// ---------------- scratch (device globals, no allocation allowed) ----------------
__device__ float  g_score[ROWS];
__device__ float  g_s[ROWS];
__device__ float4 g_lbox[ROWS];
__device__ float4 g_rbox[ROWS];
__device__ int    g_order[ROWS];
__device__ float  g_ssort[ROWS];
__device__ float4 g_sboxL[ROWS];
__device__ float4 g_sboxR[ROWS];
__device__ unsigned g_bar_arrive;
__device__ unsigned g_bar_gen;     // monotonic across replays - OK

__device__ __forceinline__ float NEGINF() { return __int_as_float(0xff800000); }

__device__ __forceinline__ void grid_barrier() {
    __syncthreads();
    if (threadIdx.x == 0) {
        __threadfence();
        unsigned gen = *(volatile unsigned*)&g_bar_gen;
        __threadfence();
        if (atomicAdd(&g_bar_arrive, 1u) == NBLK - 1) {
            *(volatile unsigned*)&g_bar_arrive = 0u;
            __threadfence();
            atomicAdd(&g_bar_gen, 1u);
        } else {
            while (*(volatile unsigned*)&g_bar_gen == gen) { __nanosleep(64); }
            __threadfence();
        }
    }
    __syncthreads();
}

__device__ __forceinline__ float box_area(float4 a) {
    return fmaxf(__fadd_rn(__fsub_rn(a.z, a.x), 1.0f), 0.0f) *
           fmaxf(__fadd_rn(__fsub_rn(a.w, a.y), 1.0f), 0.0f);
}

__device__ __forceinline__ bool iou_gt(float4 a, float areaA, float4 b) {
    float areaB = box_area(b);
    float lx = fmaxf(a.x, b.x), ly = fmaxf(a.y, b.y);
    float rx = fminf(a.z, b.z), ry = fminf(a.w, b.w);
    float iw = fmaxf(__fadd_rn(__fsub_rn(rx, lx), 1.0f), 0.0f);
    float ih = fmaxf(__fadd_rn(__fsub_rn(ry, ly), 1.0f), 0.0f);
    float inter = __fmul_rn(iw, ih);
    float uni = fmaxf(__fsub_rn(__fadd_rn(areaA, areaB), inter), 1e-6f);
    return __fdiv_rn(inter, uni) > NMS_THRESH;
}

__device__ __forceinline__ float4 decode_clip(float4 r, float4 p, float W1, float H1) {
    float w  = p.z - p.x + 1.0f;
    float h  = p.w - p.y + 1.0f;
    float cx = p.x + 0.5f * w;
    float cy = p.y + 0.5f * h;
    float dx = r.x / 10.0f;
    float dy = r.y / 10.0f;
    float dw = fminf(r.z / 5.0f, BBOX_CLIP);
    float dh = fminf(r.w / 5.0f, BBOX_CLIP);
    float pcx = dx * w + cx;
    float pcy = dy * h + cy;
    float pw = expf(dw) * w;
    float ph = expf(dh) * h;
    float x1 = pcx - 0.5f * pw;
    float y1 = pcy - 0.5f * ph;
    float x2 = pcx + 0.5f * pw - 1.0f;
    float y2 = pcy + 0.5f * ph - 1.0f;
    float4 o;
    o.x = fminf(fmaxf(x1, 0.0f), W1);
    o.y = fminf(fmaxf(y1, 0.0f), H1);
    o.z = fminf(fmaxf(x2, 0.0f), W1);
    o.w = fminf(fmaxf(y2, 0.0f), H1);
    return o;
}

// on-the-fly suppression row (fallback path), word `lane` of row i
__device__ unsigned long long onfly_row(const float4* boxes, int i, int lane) {
    float4 a = boxes[i];
    float areaA = box_area(a);
    unsigned long long bits = 0;
    int jbase = lane << 6;
    for (int jj = 0; jj < 64; jj++) {
        int j = jbase + jj;
        if (j <= i) continue;
        if (iou_gt(a, areaA, boxes[j])) bits |= (1ull << jj);
    }
    return bits;
}

__device__ __forceinline__ unsigned ordered_u(float s) {
    unsigned u = __float_as_uint(s);
    return (u & 0x80000000u) ? ~u : (u | 0x80000000u);
}
__device__ __forceinline__ unsigned long long sort_key(float s, int idx) {
    return ((unsigned long long)ordered_u(s) << 32) | (unsigned)(0xFFFFFFFFu - (unsigned)idx);
}

// block-wide descending bitonic sort, n power of two
__device__ void bitonic_desc(unsigned long long* k, int n) {
    int tid = threadIdx.x;
    int jp = 32;
    for (int kk = 2; kk <= n; kk <<= 1) {
        for (int j = kk >> 1; j > 0; j >>= 1) {
            if (j >= 32 || jp >= 32) __syncthreads(); else __syncwarp();
            for (int t = tid; t < n; t += NTHR) {
                int ixj = t ^ j;
                if (ixj > t) {
                    unsigned long long a = k[t], b = k[ixj];
                    bool sw = ((t & kk) == 0) ? (a < b) : (a > b);
                    if (sw) { k[t] = b; k[ixj] = a; }
                }
            }
            jp = j;
        }
    }
    __syncthreads();
}

// fallback: full exact sort of all NN positions (block-wide)
__device__ void full_sort_block(int img, unsigned long long* keyF) {
    int tid = threadIdx.x;
    for (int p = tid; p < NN; p += NTHR) keyF[p] = sort_key(g_s[img * NN + p], p);
    __syncthreads();
    bitonic_desc(keyF, NN);
    for (int p = tid; p < NN; p += NTHR) {
        unsigned long long kk = keyF[p];
        int local = (int)(0xFFFFFFFFu - (unsigned)(kk & 0xFFFFFFFFu));
        int g = img * NN + local;
        g_order[img * NN + p] = local;
        g_ssort[img * NN + p] = g_s[g];
        g_sboxL[img * NN + p] = g_lbox[g];
        g_sboxR[img * NN + p] = g_rbox[g];
    }
    __syncthreads();
}

__global__ void __launch_bounds__(NTHR, 1)
fused_kernel(const float* __restrict__ logits,
             const float* __restrict__ reg,
             const float* __restrict__ lp,
             const float* __restrict__ rp,
             float* __restrict__ out) {
    __shared__ __align__(16) char arena[32768];          // hist | sbox+smask | fallback keys
    __shared__ unsigned long long keySel[SSEL];          // 4 KB
    __shared__ unsigned long long nzS[2][WP];
    __shared__ unsigned long long aliveSh[2][32];
    __shared__ unsigned long long jointSh[32];
    __shared__ float kthSh;
    __shared__ int stopSh, cntSh, limitSh, nSelSh, cutSh, selCntSh, svSh;

    const int blk = blockIdx.x;
    const int tid = threadIdx.x;
    const int lane = tid & 31;
    const int gid = blk * NTHR + tid;

    // ---------------- phase 0: zero output ----------------
    for (int k = gid; k < BB * NN * 9; k += NBLK * NTHR) out[k] = 0.0f;

    // ---------------- phase 1: softmax score + argmax + decode + clip (pipelined) ------
    {
        int gwarp = gid >> 5;
        float v0[RPW], v1[RPW], v2[RPW];
        #pragma unroll
        for (int it = 0; it < RPW; it++) {
            int row = gwarp + it * NWARPS;
            const float* lrow = logits + (size_t)row * CC;
            v0[it] = lrow[lane];
            v1[it] = lrow[lane + 32];
            v2[it] = (lane < CC - 64) ? lrow[lane + 64] : NEGINF();
        }
        int bis[RPW];
        float sc[RPW];
        #pragma unroll
        for (int it = 0; it < RPW; it++) {
            float bv = v0[it]; int bi = lane;
            if (v1[it] > bv) { bv = v1[it]; bi = lane + 32; }
            if (v2[it] > bv) { bv = v2[it]; bi = lane + 64; }
            #pragma unroll
            for (int o = 16; o; o >>= 1) {
                float ov = __shfl_xor_sync(0xffffffffu, bv, o);
                int   oi = __shfl_xor_sync(0xffffffffu, bi, o);
                if (ov > bv || (ov == bv && oi < bi)) { bv = ov; bi = oi; }
            }
            float e = expf(v0[it] - bv) + expf(v1[it] - bv) +
                      ((lane < CC - 64) ? expf(v2[it] - bv) : 0.0f);
            #pragma unroll
            for (int o = 16; o; o >>= 1) e += __shfl_xor_sync(0xffffffffu, e, o);
            bis[it] = bi;
            sc[it] = __fdiv_rn(1.0f, e);
        }
        if (lane == 0 || lane == 16) {
            float4 rv[RPW], pp[RPW];
            #pragma unroll
            for (int it = 0; it < RPW; it++) {
                int row = gwarp + it * NWARPS;
                const float* rr = reg + (size_t)row * (CC * 8) + bis[it] * 8 + (lane == 16 ? 4 : 0);
                rv[it] = *(const float4*)rr;
                pp[it] = (lane == 0) ? ((const float4*)lp)[row] : ((const float4*)rp)[row];
            }
            #pragma unroll
            for (int it = 0; it < RPW; it++) {
                int row = gwarp + it * NWARPS;
                float4 box = decode_clip(rv[it], pp[it], IMG_W - 1.0f, IMG_H - 1.0f);
                if (lane == 0) {
                    g_lbox[row] = box;
                    g_score[row] = sc[it];
                    bool valid = (bis[it] >= 1) && (sc[it] > SCORE_THRESH);
                    g_s[row] = valid ? sc[it] : NEGINF();
                } else {
                    g_rbox[row] = box;
                }
            }
        }
    }
    grid_barrier();
    if (blk >= BB) return;

    // =========== image block: selection -> prefix mask -> early-stop scan ===========
    const int img = blk;
    int* hist  = (int*)arena;
    int* hist2 = hist + 2048;
    float4* sboxLS = (float4*)arena;                              // 8 KB (after hist dead)
    float4* sboxRS = sboxLS + SSEL;                               // 8 KB
    unsigned long long* smaskS = (unsigned long long*)(arena + 16384);  // 16 KB
    unsigned long long* keyF = (unsigned long long*)arena;        // fallback keys (16 KB)

    // ---- top-K selection via 2048-bin histogram of ordered score ----
    for (int b = tid; b < 2048; b += NTHR) hist[b] = 0;
    if (tid < 2 * WP) ((unsigned long long*)nzS)[tid] = 0ull;
    if (tid < 32) { jointSh[tid] = 0; aliveSh[0][tid] = 0; aliveSh[1][tid] = 0; }
    if (tid == 0) { stopSh = 0; cntSh = 0; kthSh = NEGINF(); selCntSh = 0; cutSh = 4; }
    __syncthreads();
    #pragma unroll
    for (int q = 0; q < 2; q++) {
        int p = tid + q * NTHR;
        unsigned u = ordered_u(g_s[img * NN + p]);
        atomicAdd(&hist[u >> 21], 1);
    }
    __syncthreads();
    // inclusive suffix-sum (Hillis-Steele, 11 rounds, ping-pong)
    int* src = hist; int* dst = hist2;
    for (int d = 1; d < 2048; d <<= 1) {
        for (int b = tid; b < 2048; b += NTHR)
            dst[b] = src[b] + ((b + d < 2048) ? src[b + d] : 0);
        __syncthreads();
        int* t = src; src = dst; dst = t;
    }
    // cutoff: largest bin b>=4 with suffix(b) >= TSEL
    #pragma unroll
    for (int q = 0; q < 2; q++) {
        int b = tid + q * NTHR;
        if (b >= 4 && src[b] >= TSEL && (b == 2047 || src[b + 1] < TSEL)) cutSh = b;
    }
    __syncthreads();
    if (tid == 0) { limitSh = src[4]; nSelSh = src[cutSh]; }
    __syncthreads();
    const int limit = limitSh;
    int nSel = nSelSh;
    const int cut = cutSh;
    if (nSel > limit) nSel = limit;

    if (nSel <= SSEL) {
        // collect items with bin >= cut (exact global top-nSel set)
        #pragma unroll
        for (int q = 0; q < 2; q++) {
            int p = tid + q * NTHR;
            unsigned u = ordered_u(g_s[img * NN + p]);
            if ((int)(u >> 21) >= cut) {
                int slot = atomicAdd(&selCntSh, 1);
                keySel[slot] = ((unsigned long long)u << 32) |
                               (unsigned)(0xFFFFFFFFu - (unsigned)p);
            }
        }
        __syncthreads();
        for (int t = tid; t < SSEL; t += NTHR) if (t >= selCntSh) keySel[t] = 0ull;
        __syncthreads();
        bitonic_desc(keySel, SSEL);
        // write sorted prefix (smem boxes + global order/score arrays)
        for (int p = tid; p < nSel; p += NTHR) {
            unsigned long long kk = keySel[p];
            int local = (int)(0xFFFFFFFFu - (unsigned)(kk & 0xFFFFFFFFu));
            int g = img * NN + local;
            g_order[img * NN + p] = local;
            g_ssort[img * NN + p] = g_s[g];
            sboxLS[p] = g_lbox[g];
            sboxRS[p] = g_rbox[g];
        }
        if (tid == 0) svSh = nSel;
    } else {
        // pathological tie overflow: exact full sort, then fill prefix smem
        full_sort_block(img, keyF);
        for (int p = tid; p < SSEL; p += NTHR) {
            sboxLS[p] = g_sboxL[img * NN + p];
            sboxRS[p] = g_sboxR[img * NN + p];
        }
        if (tid == 0) svSh = NN;
    }
    __syncthreads();

    // ---- prefix suppression mask (256x256, both sides) into smem ----
    {
        int side = tid >> 9;                 // 0..1
        int i    = (tid >> 1) & 255;
        int half = tid & 1;                  // cols [0,128) or [128,256)
        int limitP = limit < P_ ? limit : P_;
        const float4* bb = side ? sboxRS : sboxLS;
        unsigned long long b0 = 0, b1 = 0;
        int w0 = half * 2;
        if (i < limitP) {
            float4 a = bb[i];
            float areaA = box_area(a);
            #pragma unroll
            for (int wq = 0; wq < 2; wq++) {
                int w = w0 + wq;
                unsigned long long bits = 0;
                int jbase = w << 6;
                #pragma unroll 8
                for (int jj = 0; jj < 64; jj++) {
                    int j = jbase + jj;
                    if (j <= i) continue;
                    if (iou_gt(a, areaA, bb[j])) bits |= (1ull << jj);
                }
                smaskS[(side * 256 + i) * 4 + w] = bits;
                if (wq == 0) b0 = bits; else b1 = bits;
            }
        } else {
            smaskS[(side * 256 + i) * 4 + w0] = 0ull;
            smaskS[(side * 256 + i) * 4 + w0 + 1] = 0ull;
        }
        unsigned long long any = b0 | b1;
        any |= __shfl_xor_sync(0xffffffffu, any, 1);
        if (half == 0 && any) atomicOr(&nzS[side][i >> 6], 1ull << (i & 63));
    }
    __syncthreads();

    // ---- early-terminating joint greedy scan ----
    int warp = tid >> 5;
    unsigned long long alive = 0, nzreg = 0;
    const float4* boxesG = 0;
    if (warp < 2) {
        boxesG = (warp == 0 ? g_sboxL : g_sboxR) + img * NN;
        nzreg = (lane < WP) ? nzS[warp][lane] : 0ull;
        int lo = lane << 6;
        alive = (limit >= lo + 64) ? ~0ull
              : (limit <= lo ? 0ull : ((1ull << (limit - lo)) - 1ull));
    }
    bool missedDone = false;
    for (int w = 0; w < 32; w++) {
        if (w == WP) {   // need order beyond prefix -> exact full sort (rarely taken)
            __syncthreads();
            if (svSh < NN) {
                full_sort_block(img, keyF);
                __syncthreads();
                if (tid == 0) svSh = NN;
            }
            __syncthreads();
        }
        if (warp < 2) {
            if (w < WP) {
                unsigned long long work = __shfl_sync(0xffffffffu, alive & nzreg, w);
                const unsigned long long* base = smaskS + (size_t)warp * 256 * 4;
                unsigned long long supp = 0;
                while (work) {
                    int i = __ffsll((long long)work) - 1;
                    work &= work - 1;
                    int row = (w << 6) + i;                      // ABSOLUTE row (bugfix)
                    unsigned long long rv = (lane < WP) ? base[row * 4 + lane] : 0ull;
                    unsigned long long ww = base[row * 4 + w];
                    supp |= rv;
                    work &= ~ww;
                }
                alive &= ~supp;
            } else {
                if (!missedDone) {
                    missedDone = true;
                    for (int pw = 0; pw < WP; pw++) {
                        unsigned long long kk = __shfl_sync(0xffffffffu, alive, pw);
                        while (kk) {
                            int ii = __ffsll((long long)kk) - 1; kk &= kk - 1;
                            unsigned long long ww = onfly_row(boxesG, pw * 64 + ii, lane);
                            if (lane >= WP) alive &= ~ww;
                        }
                    }
                }
                unsigned long long work = __shfl_sync(0xffffffffu, alive, w);
                unsigned long long supp = 0;
                while (work) {
                    int i = __ffsll((long long)work) - 1;
                    work &= work - 1;
                    unsigned long long ww = onfly_row(boxesG, w * 64 + i, lane);
                    supp |= ww;
                    unsigned long long www = __shfl_sync(0xffffffffu, ww, w);
                    work &= ~www;
                }
                alive &= ~supp;
            }
            if (lane == w) aliveSh[warp][w] = alive;
        }
        __syncthreads();
        if (tid == 0) {
            unsigned long long jw = aliveSh[0][w] & aliveSh[1][w];
            jointSh[w] = jw;
            int pc = __popcll(jw);
            int cnt = cntSh;
            if (cnt < DETS_PER_IMG && cnt + pc >= DETS_PER_IMG) {
                int need = DETS_PER_IMG - cnt;
                unsigned long long t = jw; int b = -1;
                while (need--) { b = __ffsll((long long)t) - 1; t &= t - 1; }
                kthSh = g_ssort[img * NN + w * 64 + b];
            }
            cnt += pc; cntSh = cnt;
            int nxt = (w + 1) * 64;
            bool fin = (nxt >= limit);
            if (!fin && cnt >= DETS_PER_IMG && nxt < svSh &&
                g_ssort[img * NN + nxt] < kthSh) fin = true;
            stopSh = fin ? 1 : 0;
        }
        __syncthreads();
        if (stopSh) break;
    }

    float kth = kthSh;
    for (int p = tid; p < NN; p += NTHR) {
        if (!((jointSh[p >> 6] >> (p & 63)) & 1ull)) continue;
        float s = g_ssort[img * NN + p];
        if (s >= kth) {
            int g = img * NN + g_order[img * NN + p];
            float4 lb = g_lbox[g], rb = g_rbox[g];
            float* o = out + (size_t)g * 9;
            o[0] = lb.x; o[1] = lb.y; o[2] = lb.z; o[3] = lb.w;
            o[4] = rb.x; o[5] = rb.y; o[6] = rb.z; o[7] = rb.w;
            o[8] = g_score[g];
        }
    }
}

// ---------------- launch ----------------
extern "C" void kernel_launch(void* const* d_in, const int* in_sizes, int n_in,
                              void* d_out, int out_size) {
    const float* logits = (const float*)d_in[0];
    const float* reg    = (const float*)d_in[1];
    const float* lp     = (const float*)d_in[2];
    const float* rp     = (const float*)d_in[3];
    float* out = (float*)d_out;
    fused_kernel<<<NBLK, NTHR>>>(logits, reg, lp, rp, out);
}

// round 13
// speedup vs baseline: 1.8218x; 1.8218x over previous
#include <cuda_runtime.h>
#include <math.h>

#define BB 4
#define NN 2048
#define CC 81
#define ROWS (BB * NN)          // 8192
#define IMG_W 1024.0f
#define IMG_H 800.0f
#define SCORE_THRESH 0.05f
#define NMS_THRESH 0.5f
#define DETS_PER_IMG 100
#define BBOX_CLIP 4.135166556742356f
#define P_  256                 // NMS mask prefix length
#define WP  (P_ / 64)           // 4 words per prefix row
#define SSEL 512                // selection capacity
#define TSEL 320                // selection target (>= P_ + margin)
#define NBLK 128
#define NTHR 1024
#define NWARPS (NBLK * NTHR / 32)   // 4096
#define RPW (ROWS / NWARPS)         // 2 rows per warp

// ---------------- scratch (device globals, no allocation allowed) ----------------
__device__ float  g_score[ROWS];
__device__ float  g_s[ROWS];
__device__ float4 g_lbox[ROWS];
__device__ float4 g_rbox[ROWS];
__device__ int    g_order[ROWS];
__device__ float  g_ssort[ROWS];
__device__ float4 g_sboxL[ROWS];
__device__ float4 g_sboxR[ROWS];
__device__ int    g_nvalid[BB];
__device__ int    g_sv[BB];                                       // sorted-valid prefix length
__device__ unsigned long long g_mask[(size_t)2 * BB * P_ * WP];   // 64 KB prefix bitmask
__device__ unsigned long long g_nz[2][BB][WP];
__device__ unsigned g_bar_arrive;
__device__ unsigned g_bar_gen;       // monotonic across replays - OK
__device__ unsigned g_sort_done[BB]; // monotonic per-image counters
__device__ unsigned g_mask_done[BB];

__device__ __forceinline__ float NEGINF() { return __int_as_float(0xff800000); }

__device__ __forceinline__ void grid_barrier() {
    __syncthreads();
    if (threadIdx.x == 0) {
        __threadfence();
        unsigned gen = *(volatile unsigned*)&g_bar_gen;
        __threadfence();
        if (atomicAdd(&g_bar_arrive, 1u) == NBLK - 1) {
            *(volatile unsigned*)&g_bar_arrive = 0u;
            __threadfence();
            atomicAdd(&g_bar_gen, 1u);
        } else {
            while (*(volatile unsigned*)&g_bar_gen == gen) { __nanosleep(64); }
            __threadfence();
        }
    }
    __syncthreads();
}

__device__ __forceinline__ void cp_async8(void* dst, const void* src) {
    unsigned d = (unsigned)__cvta_generic_to_shared(dst);
    asm volatile("cp.async.ca.shared.global [%0], [%1], 8;" :: "r"(d), "l"(src));
}
#define CP_COMMIT() asm volatile("cp.async.commit_group;" ::: "memory")
#define CP_WAIT(n)  asm volatile("cp.async.wait_group %0;" :: "n"(n) : "memory")

__device__ __forceinline__ float box_area(float4 a) {
    return fmaxf(__fadd_rn(__fsub_rn(a.z, a.x), 1.0f), 0.0f) *
           fmaxf(__fadd_rn(__fsub_rn(a.w, a.y), 1.0f), 0.0f);
}

__device__ __forceinline__ bool iou_gt(float4 a, float areaA, float4 b) {
    float areaB = box_area(b);
    float lx = fmaxf(a.x, b.x), ly = fmaxf(a.y, b.y);
    float rx = fminf(a.z, b.z), ry = fminf(a.w, b.w);
    float iw = fmaxf(__fadd_rn(__fsub_rn(rx, lx), 1.0f), 0.0f);
    float ih = fmaxf(__fadd_rn(__fsub_rn(ry, ly), 1.0f), 0.0f);
    float inter = __fmul_rn(iw, ih);
    float uni = fmaxf(__fsub_rn(__fadd_rn(areaA, areaB), inter), 1e-6f);
    return __fdiv_rn(inter, uni) > NMS_THRESH;
}

__device__ __forceinline__ float4 decode_clip(float4 r, float4 p, float W1, float H1) {
    float w  = p.z - p.x + 1.0f;
    float h  = p.w - p.y + 1.0f;
    float cx = p.x + 0.5f * w;
    float cy = p.y + 0.5f * h;
    float dx = r.x / 10.0f;
    float dy = r.y / 10.0f;
    float dw = fminf(r.z / 5.0f, BBOX_CLIP);
    float dh = fminf(r.w / 5.0f, BBOX_CLIP);
    float pcx = dx * w + cx;
    float pcy = dy * h + cy;
    float pw = expf(dw) * w;
    float ph = expf(dh) * h;
    float x1 = pcx - 0.5f * pw;
    float y1 = pcy - 0.5f * ph;
    float x2 = pcx + 0.5f * pw - 1.0f;
    float y2 = pcy + 0.5f * ph - 1.0f;
    float4 o;
    o.x = fminf(fmaxf(x1, 0.0f), W1);
    o.y = fminf(fmaxf(y1, 0.0f), H1);
    o.z = fminf(fmaxf(x2, 0.0f), W1);
    o.w = fminf(fmaxf(y2, 0.0f), H1);
    return o;
}

__device__ unsigned long long onfly_row(const float4* boxes, int i, int lane) {
    float4 a = boxes[i];
    float areaA = box_area(a);
    unsigned long long bits = 0;
    int jbase = lane << 6;
    for (int jj = 0; jj < 64; jj++) {
        int j = jbase + jj;
        if (j <= i) continue;
        if (iou_gt(a, areaA, boxes[j])) bits |= (1ull << jj);
    }
    return bits;
}

__device__ __forceinline__ unsigned ordered_u(float s) {
    unsigned u = __float_as_uint(s);
    return (u & 0x80000000u) ? ~u : (u | 0x80000000u);
}
__device__ __forceinline__ unsigned long long sort_key(float s, int idx) {
    return ((unsigned long long)ordered_u(s) << 32) | (unsigned)(0xFFFFFFFFu - (unsigned)idx);
}

// block-wide descending bitonic sort, n power of two
__device__ void bitonic_desc(unsigned long long* k, int n) {
    int tid = threadIdx.x;
    int jp = 32;
    for (int kk = 2; kk <= n; kk <<= 1) {
        for (int j = kk >> 1; j > 0; j >>= 1) {
            if (j >= 32 || jp >= 32) __syncthreads(); else __syncwarp();
            for (int t = tid; t < n; t += NTHR) {
                int ixj = t ^ j;
                if (ixj > t) {
                    unsigned long long a = k[t], b = k[ixj];
                    bool sw = ((t & kk) == 0) ? (a < b) : (a > b);
                    if (sw) { k[t] = b; k[ixj] = a; }
                }
            }
            jp = j;
        }
    }
    __syncthreads();
}

// fallback: full exact sort of all NN positions (block-wide)
__device__ void full_sort_block(int img, unsigned long long* keyF) {
    int tid = threadIdx.x;
    for (int p = tid; p < NN; p += NTHR) keyF[p] = sort_key(g_s[img * NN + p], p);
    __syncthreads();
    bitonic_desc(keyF, NN);
    for (int p = tid; p < NN; p += NTHR) {
        unsigned long long kk = keyF[p];
        int local = (int)(0xFFFFFFFFu - (unsigned)(kk & 0xFFFFFFFFu));
        int g = img * NN + local;
        g_order[img * NN + p] = local;
        g_ssort[img * NN + p] = g_s[g];
        g_sboxL[img * NN + p] = g_lbox[g];
        g_sboxR[img * NN + p] = g_rbox[g];
    }
    __syncthreads();
}

__global__ void __launch_bounds__(NTHR, 1)
fused_kernel(const float* __restrict__ logits,
             const float* __restrict__ reg,
             const float* __restrict__ lp,
             const float* __restrict__ rp,
             float* __restrict__ out) {
    __shared__ __align__(16) char arena[16384];          // hist ping-pong / fallback keys
    __shared__ unsigned long long keySel[SSEL];          // 4 KB
    __shared__ float4 sj[64];                            // mask blocks
    __shared__ unsigned long long buf[2][2][64 * WP];    // scan cp.async staging (8 KB)
    __shared__ unsigned long long aliveSh[2][32];
    __shared__ unsigned long long jointSh[32];
    __shared__ float kthSh;
    __shared__ int stopSh, cntSh, cutSh, selCntSh, svSh;
    __shared__ unsigned baseSh;

    const int blk = blockIdx.x;
    const int tid = threadIdx.x;
    const int lane = tid & 31;
    const int gid = blk * NTHR + tid;

    // capture per-launch flag bases BEFORE any producer can increment (pre-barrier)
    if (tid == 0) {
        if (blk < BB) baseSh = g_mask_done[blk];
        else if (blk < 4 + 32) baseSh = g_sort_done[((blk - 4) >> 2) & 3];
    }

    // ---------------- phase 0: zero output + flags ----------------
    for (int k = gid; k < BB * NN * 9; k += NBLK * NTHR) out[k] = 0.0f;
    if (blk == 0 && tid < 2 * BB * WP) ((unsigned long long*)g_nz)[tid] = 0ull;

    // ---------------- phase 1: softmax score + argmax + decode + clip (pipelined) ------
    {
        int gwarp = gid >> 5;
        float v0[RPW], v1[RPW], v2[RPW];
        #pragma unroll
        for (int it = 0; it < RPW; it++) {
            int row = gwarp + it * NWARPS;
            const float* lrow = logits + (size_t)row * CC;
            v0[it] = lrow[lane];
            v1[it] = lrow[lane + 32];
            v2[it] = (lane < CC - 64) ? lrow[lane + 64] : NEGINF();
        }
        int bis[RPW];
        float sc[RPW];
        #pragma unroll
        for (int it = 0; it < RPW; it++) {
            float bv = v0[it]; int bi = lane;
            if (v1[it] > bv) { bv = v1[it]; bi = lane + 32; }
            if (v2[it] > bv) { bv = v2[it]; bi = lane + 64; }
            #pragma unroll
            for (int o = 16; o; o >>= 1) {
                float ov = __shfl_xor_sync(0xffffffffu, bv, o);
                int   oi = __shfl_xor_sync(0xffffffffu, bi, o);
                if (ov > bv || (ov == bv && oi < bi)) { bv = ov; bi = oi; }
            }
            float e = expf(v0[it] - bv) + expf(v1[it] - bv) +
                      ((lane < CC - 64) ? expf(v2[it] - bv) : 0.0f);
            #pragma unroll
            for (int o = 16; o; o >>= 1) e += __shfl_xor_sync(0xffffffffu, e, o);
            bis[it] = bi;
            sc[it] = __fdiv_rn(1.0f, e);
        }
        if (lane == 0 || lane == 16) {
            float4 rv[RPW], pp[RPW];
            #pragma unroll
            for (int it = 0; it < RPW; it++) {
                int row = gwarp + it * NWARPS;
                const float* rr = reg + (size_t)row * (CC * 8) + bis[it] * 8 + (lane == 16 ? 4 : 0);
                rv[it] = *(const float4*)rr;
                pp[it] = (lane == 0) ? ((const float4*)lp)[row] : ((const float4*)rp)[row];
            }
            #pragma unroll
            for (int it = 0; it < RPW; it++) {
                int row = gwarp + it * NWARPS;
                float4 box = decode_clip(rv[it], pp[it], IMG_W - 1.0f, IMG_H - 1.0f);
                if (lane == 0) {
                    g_lbox[row] = box;
                    g_score[row] = sc[it];
                    bool valid = (bis[it] >= 1) && (sc[it] > SCORE_THRESH);
                    g_s[row] = valid ? sc[it] : NEGINF();
                } else {
                    g_rbox[row] = box;
                }
            }
        }
    }
    grid_barrier();   // the ONLY grid barrier

    // ---------------- mask blocks (4..35): wait per-image sort flag, compute prefix ----
    if (blk >= 4 && blk < 36) {
        int idx = blk - 4;
        int side = idx >> 4;
        int img  = (idx >> 2) & 3;
        int w    = idx & 3;
        if (tid == 0) {
            unsigned base = baseSh;
            while ((int)(*(volatile unsigned*)&g_sort_done[img] - base) < 1) __nanosleep(32);
            __threadfence();
        }
        __syncthreads();
        int limit = g_nvalid[img];
        int jbase = w << 6;
        const float4* boxes = (side == 0 ? g_sboxL : g_sboxR) + img * NN;
        if (jbase < limit) {
            if (tid < 64) sj[tid] = boxes[jbase + tid];
            __syncthreads();
            int ib  = tid >> 8;                          // 0..3
            int r   = (tid >> 2) & 63;
            int sub = tid & 3;
            int i = ib * 64 + r;
            unsigned long long partial = 0;
            if (ib <= w && i < limit) {                  // upper-triangle blocks only
                float4 a = boxes[i];
                float areaA = box_area(a);
                int j0 = sub * 16;
                #pragma unroll
                for (int jj = j0; jj < j0 + 16; jj++) {
                    int j = jbase + jj;
                    if (j <= i) continue;
                    if (iou_gt(a, areaA, sj[jj])) partial |= (1ull << jj);
                }
            }
            partial |= __shfl_xor_sync(0xffffffffu, partial, 1);
            partial |= __shfl_xor_sync(0xffffffffu, partial, 2);
            if (sub == 0 && partial) {
                g_mask[((size_t)(side * BB + img) * P_ + i) * WP + w] = partial;
                atomicOr(&g_nz[side][img][i >> 6], 1ull << (i & 63));
            }
        }
        __threadfence();
        __syncthreads();
        if (tid == 0) atomicAdd(&g_mask_done[img], 1u);
        return;
    }
    if (blk >= 36) return;

    // ======== image blocks (0..3): histogram top-K selection -> flag -> scan ========
    const int img = blk;
    int* hist  = (int*)arena;
    int* hist2 = hist + 2048;
    unsigned long long* keyF = (unsigned long long*)arena;   // fallback keys (16 KB)

    // ---- top-K selection via 2048-bin histogram of ordered score ----
    for (int b = tid; b < 2048; b += NTHR) hist[b] = 0;
    if (tid < 32) { jointSh[tid] = 0; aliveSh[0][tid] = 0; aliveSh[1][tid] = 0; }
    if (tid == 0) { stopSh = 0; cntSh = 0; kthSh = NEGINF(); selCntSh = 0; cutSh = 4; }
    __syncthreads();
    #pragma unroll
    for (int q = 0; q < 2; q++) {
        int p = tid + q * NTHR;
        unsigned u = ordered_u(g_s[img * NN + p]);
        atomicAdd(&hist[u >> 21], 1);
    }
    __syncthreads();
    int* src = hist; int* dst = hist2;
    for (int d = 1; d < 2048; d <<= 1) {                 // inclusive suffix-sum
        for (int b = tid; b < 2048; b += NTHR)
            dst[b] = src[b] + ((b + d < 2048) ? src[b + d] : 0);
        __syncthreads();
        int* t = src; src = dst; dst = t;
    }
    #pragma unroll
    for (int q = 0; q < 2; q++) {                        // largest bin>=4 with suffix>=TSEL
        int b = tid + q * NTHR;
        if (b >= 4 && src[b] >= TSEL && (b == 2047 || src[b + 1] < TSEL)) cutSh = b;
    }
    __syncthreads();
    const int limit = src[4];                            // count of valid (bin >= 4)
    int nSel = src[cutSh];
    const int cut = cutSh;
    if (nSel > limit) nSel = limit;
    __syncthreads();                                     // everyone read src before reuse

    if (nSel <= SSEL) {
        #pragma unroll
        for (int q = 0; q < 2; q++) {
            int p = tid + q * NTHR;
            unsigned u = ordered_u(g_s[img * NN + p]);
            if ((int)(u >> 21) >= cut) {
                int slot = atomicAdd(&selCntSh, 1);
                keySel[slot] = ((unsigned long long)u << 32) |
                               (unsigned)(0xFFFFFFFFu - (unsigned)p);
            }
        }
        __syncthreads();
        for (int t = tid; t < SSEL; t += NTHR) if (t >= selCntSh) keySel[t] = 0ull;
        __syncthreads();
        bitonic_desc(keySel, SSEL);
        for (int p = tid; p < nSel; p += NTHR) {
            unsigned long long kk = keySel[p];
            int local = (int)(0xFFFFFFFFu - (unsigned)(kk & 0xFFFFFFFFu));
            int g = img * NN + local;
            g_order[img * NN + p] = local;
            g_ssort[img * NN + p] = g_s[g];
            g_sboxL[img * NN + p] = g_lbox[g];
            g_sboxR[img * NN + p] = g_rbox[g];
        }
        if (tid == 0) svSh = nSel;
    } else {
        full_sort_block(img, keyF);                      // pathological tie overflow
        if (tid == 0) svSh = NN;
    }
    if (tid == 0) { g_nvalid[img] = limit; g_sv[img] = svSh; }
    __threadfence();
    __syncthreads();
    if (tid == 0) atomicAdd(&g_sort_done[img], 1u);

    // wait for this image's 8 mask blocks
    if (tid == 0) {
        unsigned base = baseSh;
        while ((int)(*(volatile unsigned*)&g_mask_done[img] - base) < 8) __nanosleep(32);
        __threadfence();
    }
    __syncthreads();

    // ---------------- early-terminating joint greedy scan ----------------
    int warp = tid >> 5;
    unsigned long long alive = 0, nzreg = 0;
    const float4* boxesG = 0;
    const unsigned long long* maskBase = 0;
    if (warp < 2) {
        maskBase = g_mask + (size_t)(warp * BB + img) * P_ * WP;
        boxesG = (warp == 0 ? g_sboxL : g_sboxR) + img * NN;
        nzreg = (lane < WP) ? g_nz[warp][img][lane] : 0ull;
        int lo = lane << 6;
        alive = (limit >= lo + 64) ? ~0ull
              : (limit <= lo ? 0ull : ((1ull << (limit - lo)) - 1ull));
        unsigned long long wk = __shfl_sync(0xffffffffu, alive & nzreg, 0);
        while (wk) {
            int i = __ffsll((long long)wk) - 1; wk &= wk - 1;
            if (lane < WP) cp_async8(&buf[warp][0][i * WP + lane],
                                     maskBase + (size_t)i * WP + lane);
        }
        CP_COMMIT();
    }

    bool missedDone = false;
    for (int w = 0; w < 32; w++) {
        if (w == WP) {       // order needed beyond prefix -> exact full sort (rare)
            if (warp < 2) CP_WAIT(0);
            __syncthreads();
            if (svSh < NN) {
                full_sort_block(img, keyF);
                if (tid == 0) svSh = NN;
            }
            __syncthreads();
        }
        if (warp < 2) {
            if (w < WP) {
                if (w + 1 < WP) {
                    unsigned long long wk = __shfl_sync(0xffffffffu, alive & nzreg, w + 1);
                    unsigned long long* nb = buf[warp][(w + 1) & 1];
                    while (wk) {
                        int i = __ffsll((long long)wk) - 1; wk &= wk - 1;
                        if (lane < WP)
                            cp_async8(&nb[i * WP + lane],
                                      maskBase + (size_t)((w + 1) * 64 + i) * WP + lane);
                    }
                    CP_COMMIT(); CP_WAIT(1);
                } else {
                    CP_WAIT(0);
                }
                __syncwarp();
                unsigned long long work = __shfl_sync(0xffffffffu, alive & nzreg, w);
                unsigned long long* cur = buf[warp][w & 1];
                unsigned long long supp = 0;
                while (work) {
                    int i = __ffsll((long long)work) - 1;
                    work &= work - 1;
                    unsigned long long rv = (lane < WP) ? cur[i * WP + lane] : 0ull;
                    unsigned long long ww = cur[i * WP + w];
                    supp |= rv;
                    work &= ~ww;
                }
                alive &= ~supp;
            } else {
                if (!missedDone) {
                    missedDone = true;
                    for (int pw = 0; pw < WP; pw++) {
                        unsigned long long kk = __shfl_sync(0xffffffffu, alive, pw);
                        while (kk) {
                            int ii = __ffsll((long long)kk) - 1; kk &= kk - 1;
                            unsigned long long ww = onfly_row(boxesG, pw * 64 + ii, lane);
                            if (lane >= WP) alive &= ~ww;
                        }
                    }
                }
                unsigned long long work = __shfl_sync(0xffffffffu, alive, w);
                unsigned long long supp = 0;
                while (work) {
                    int i = __ffsll((long long)work) - 1;
                    work &= work - 1;
                    unsigned long long ww = onfly_row(boxesG, w * 64 + i, lane);
                    supp |= ww;
                    unsigned long long www = __shfl_sync(0xffffffffu, ww, w);
                    work &= ~www;
                }
                alive &= ~supp;
            }
            if (lane == w) aliveSh[warp][w] = alive;
        }
        __syncthreads();
        if (tid == 0) {
            unsigned long long jw = aliveSh[0][w] & aliveSh[1][w];
            jointSh[w] = jw;
            int pc = __popcll(jw);
            int cnt = cntSh;
            if (cnt < DETS_PER_IMG && cnt + pc >= DETS_PER_IMG) {
                int need = DETS_PER_IMG - cnt;
                unsigned long long t = jw; int b = -1;
                while (need--) { b = __ffsll((long long)t) - 1; t &= t - 1; }
                kthSh = g_ssort[img * NN + w * 64 + b];
            }
            cnt += pc; cntSh = cnt;
            int nxt = (w + 1) * 64;
            bool fin = (nxt >= limit);
            if (!fin && cnt >= DETS_PER_IMG && nxt < svSh &&
                g_ssort[img * NN + nxt] < kthSh) fin = true;
            stopSh = fin ? 1 : 0;
        }
        __syncthreads();
        if (stopSh) break;
    }
    if (warp < 2) CP_WAIT(0);

    float kth = kthSh;
    for (int p = tid; p < NN; p += NTHR) {
        if (!((jointSh[p >> 6] >> (p & 63)) & 1ull)) continue;
        float s = g_ssort[img * NN + p];
        if (s >= kth) {
            int g = img * NN + g_order[img * NN + p];
            float4 lb = g_lbox[g], rb = g_rbox[g];
            float* o = out + (size_t)g * 9;
            o[0] = lb.x; o[1] = lb.y; o[2] = lb.z; o[3] = lb.w;
            o[4] = rb.x; o[5] = rb.y; o[6] = rb.z; o[7] = rb.w;
            o[8] = g_score[g];
        }
    }
}

// ---------------- launch ----------------
extern "C" void kernel_launch(void* const* d_in, const int* in_sizes, int n_in,
                              void* d_out, int out_size) {
    const float* logits = (const float*)d_in[0];
    const float* reg    = (const float*)d_in[1];
    const float* lp     = (const float*)d_in[2];
    const float* rp     = (const float*)d_in[3];
    float* out = (float*)d_out;
    fused_kernel<<<NBLK, NTHR>>>(logits, reg, lp, rp, out);
}